// round 6
// baseline (speedup 1.0000x reference)
#include <cuda_runtime.h>
#include <math.h>
#include <stdint.h>

#define Bsz  4
#define Ntok 3072
#define DIMC 768
#define Hh   3
#define HD   256
#define BH   (Bsz * Hh)          // 12
#define Dv   262                 // HD + 6
#define DP   288                 // padded per-head dim (96*3)
#define NN   ((size_t)Ntok * Ntok)
#define KPF  786                 // DIM + 6*H

// -------- scratch (static device globals; no runtime allocation) --------
__device__ float g_QKV[3 * BH * Ntok * HD];       // [3,B,H,N,HD]   113 MB
__device__ float g_VC [BH * Ntok * DP];           // [BH,N,DP]      42.5 MB (zero-padded cols 262..287)
__device__ float g_P  [(size_t)BH * Ntok * Ntok]; // exp(scores)    453 MB
__device__ float g_rsum[BH * Ntok];
__device__ float g_csum[BH * Ntok];
__device__ float g_rinv[BH * Ntok];
__device__ float g_cinv[BH * Ntok];
__device__ float g_f1 [BH * DP * Ntok];           // [BH,DP,N]      42.5 MB
__device__ float g_fund[BH * DP * DP];            // [BH,DP,DP]

// ---------------------------------------------------------------- zero sums
__global__ void k_zero() {
    int i = blockIdx.x * 256 + threadIdx.x;
    if (i < BH * Ntok) { g_rsum[i] = 0.f; g_csum[i] = 0.f; }
}

// ---------------------------------------------------------------- QKV GEMM
// C[12288, 2304] = x @ Wqkv^T   (both operands row-major [rows, K=768])
__global__ __launch_bounds__(256) void k_qkv(const float* __restrict__ x,
                                             const float* __restrict__ Wqkv) {
    __shared__ float As[8][128];
    __shared__ float Bs[8][128];
    const int tid  = threadIdx.x;
    const int m0   = blockIdx.y * 128;
    const int n0   = blockIdx.x * 128;
    const int lrow = tid >> 1;
    const int lseg = (tid & 1) * 4;
    const int ty   = tid >> 4, tx = tid & 15;
    float acc[8][8];
    #pragma unroll
    for (int i = 0; i < 8; i++)
        #pragma unroll
        for (int j = 0; j < 8; j++) acc[i][j] = 0.f;

    for (int k0 = 0; k0 < 768; k0 += 8) {
        float4 av = *(const float4*)&x   [(size_t)(m0 + lrow) * 768 + k0 + lseg];
        float4 bv = *(const float4*)&Wqkv[(size_t)(n0 + lrow) * 768 + k0 + lseg];
        __syncthreads();
        As[lseg+0][lrow]=av.x; As[lseg+1][lrow]=av.y; As[lseg+2][lrow]=av.z; As[lseg+3][lrow]=av.w;
        Bs[lseg+0][lrow]=bv.x; Bs[lseg+1][lrow]=bv.y; Bs[lseg+2][lrow]=bv.z; Bs[lseg+3][lrow]=bv.w;
        __syncthreads();
        #pragma unroll
        for (int kk = 0; kk < 8; kk++) {
            float4 a0 = *(const float4*)&As[kk][ty*8];
            float4 a1 = *(const float4*)&As[kk][ty*8+4];
            float4 b0 = *(const float4*)&Bs[kk][tx*8];
            float4 b1 = *(const float4*)&Bs[kk][tx*8+4];
            float ar[8] = {a0.x,a0.y,a0.z,a0.w,a1.x,a1.y,a1.z,a1.w};
            float br[8] = {b0.x,b0.y,b0.z,b0.w,b1.x,b1.y,b1.z,b1.w};
            #pragma unroll
            for (int i = 0; i < 8; i++)
                #pragma unroll
                for (int j = 0; j < 8; j++) acc[i][j] += ar[i] * br[j];
        }
    }
    #pragma unroll
    for (int i = 0; i < 8; i++) {
        int m  = m0 + ty * 8 + i;
        int bq = m / Ntok, n = m % Ntok;
        #pragma unroll
        for (int j = 0; j < 8; j++) {
            int c = n0 + tx * 8 + j;
            int t = c / 768, r = c % 768;
            int h = r >> 8, d = r & 255;
            g_QKV[(((size_t)(t * Bsz + bq) * Hh + h) * Ntok + n) * HD + d] = acc[i][j];
        }
    }
}

// ---------------------------------------------------------------- v_cat build
__global__ void k_vcat() {
    int i = blockIdx.x * 256 + threadIdx.x;
    const int total = BH * Ntok * DP;
    if (i >= total) return;
    int j    = i % DP;
    int rest = i / DP;
    int n    = rest % Ntok;
    int bh   = rest / Ntok;
    float val;
    if (j < 256) {
        val = g_QKV[((size_t)(2 * BH + bh) * Ntok + n) * HD + j];
    } else if (j < 262) {
        float p3 = -1.f + 2.f * (float)(n % 48) / 47.f;
        float p4 = -1.f + 2.f * (float)(n / 48) / 63.f;
        int c = j - 256;
        val = (c == 0) ? p3 * p3 :
              (c == 1) ? p4 * p4 :
              (c == 2) ? p3 * p4 :
              (c == 3) ? p3 :
              (c == 4) ? p4 : 1.f;
    } else {
        val = 0.f;
    }
    g_VC[i] = val;
}

// ---------------------------------------------------------------- scores: P = exp(Q K^T / 16); row/col sums
__global__ __launch_bounds__(256) void k_scores() {
    __shared__ float As[8][128];
    __shared__ float Bs[8][128];
    __shared__ float rAcc[128], cAcc[128];
    const int tid = threadIdx.x;
    const int bh  = blockIdx.z;
    const int m0  = blockIdx.y * 128;   // query rows (n)
    const int c0  = blockIdx.x * 128;   // key cols   (m)
    const float* Q  = g_QKV + (size_t)bh * Ntok * HD;
    const float* Km = g_QKV + (size_t)(BH + bh) * Ntok * HD;
    if (tid < 128) { rAcc[tid] = 0.f; cAcc[tid] = 0.f; }
    const int lrow = tid >> 1;
    const int lseg = (tid & 1) * 4;
    const int ty   = tid >> 4, tx = tid & 15;
    float acc[8][8];
    #pragma unroll
    for (int i = 0; i < 8; i++)
        #pragma unroll
        for (int j = 0; j < 8; j++) acc[i][j] = 0.f;

    for (int k0 = 0; k0 < HD; k0 += 8) {
        float4 av = *(const float4*)&Q [(size_t)(m0 + lrow) * HD + k0 + lseg];
        float4 bv = *(const float4*)&Km[(size_t)(c0 + lrow) * HD + k0 + lseg];
        __syncthreads();
        As[lseg+0][lrow]=av.x; As[lseg+1][lrow]=av.y; As[lseg+2][lrow]=av.z; As[lseg+3][lrow]=av.w;
        Bs[lseg+0][lrow]=bv.x; Bs[lseg+1][lrow]=bv.y; Bs[lseg+2][lrow]=bv.z; Bs[lseg+3][lrow]=bv.w;
        __syncthreads();
        #pragma unroll
        for (int kk = 0; kk < 8; kk++) {
            float4 a0 = *(const float4*)&As[kk][ty*8];
            float4 a1 = *(const float4*)&As[kk][ty*8+4];
            float4 b0 = *(const float4*)&Bs[kk][tx*8];
            float4 b1 = *(const float4*)&Bs[kk][tx*8+4];
            float ar[8] = {a0.x,a0.y,a0.z,a0.w,a1.x,a1.y,a1.z,a1.w};
            float br[8] = {b0.x,b0.y,b0.z,b0.w,b1.x,b1.y,b1.z,b1.w};
            #pragma unroll
            for (int i = 0; i < 8; i++)
                #pragma unroll
                for (int j = 0; j < 8; j++) acc[i][j] += ar[i] * br[j];
        }
    }
    // transform to exp(score)
    #pragma unroll
    for (int i = 0; i < 8; i++)
        #pragma unroll
        for (int j = 0; j < 8; j++)
            acc[i][j] = __expf(acc[i][j] * 0.0625f);

    // block-local reductions
    #pragma unroll
    for (int i = 0; i < 8; i++) {
        float rp = 0.f;
        #pragma unroll
        for (int j = 0; j < 8; j++) rp += acc[i][j];
        atomicAdd(&rAcc[ty * 8 + i], rp);
    }
    #pragma unroll
    for (int j = 0; j < 8; j++) {
        float cp = 0.f;
        #pragma unroll
        for (int i = 0; i < 8; i++) cp += acc[i][j];
        atomicAdd(&cAcc[tx * 8 + j], cp);
    }
    // store P
    #pragma unroll
    for (int i = 0; i < 8; i++) {
        size_t base = (size_t)bh * NN + (size_t)(m0 + ty * 8 + i) * Ntok + c0 + tx * 8;
        *(float4*)&g_P[base]     = make_float4(acc[i][0], acc[i][1], acc[i][2], acc[i][3]);
        *(float4*)&g_P[base + 4] = make_float4(acc[i][4], acc[i][5], acc[i][6], acc[i][7]);
    }
    __syncthreads();
    if (tid < 128) {
        atomicAdd(&g_rsum[bh * Ntok + m0 + tid], rAcc[tid]);
        atomicAdd(&g_csum[bh * Ntok + c0 + tid], cAcc[tid]);
    }
}

// ---------------------------------------------------------------- reciprocals
__global__ void k_recip() {
    int i = blockIdx.x * 256 + threadIdx.x;
    if (i < BH * Ntok) {
        g_rinv[i] = 1.f / g_rsum[i];
        g_cinv[i] = 1.f / g_csum[i];
    }
}

// ---------------------------------------------------------------- f1[dp,m] = cinv[m] * sum_n VC[n,dp] * P[n,m]^2 * rinv[n]
// BM=96 (dp), BN=128 (m), BK=8 (n), TM=6, TN=8
__global__ __launch_bounds__(256) void k_f1() {
    __shared__ float As[8][96];
    __shared__ float Bs[8][128];
    const int tid = threadIdx.x;
    const int bh  = blockIdx.z;
    const int m0  = blockIdx.x * 128;
    const int dp0 = blockIdx.y * 96;
    const float* VC   = g_VC + (size_t)bh * Ntok * DP;
    const float* P    = g_P  + (size_t)bh * NN;
    const float* rinv = g_rinv + bh * Ntok;
    const int ty = tid >> 4, tx = tid & 15;
    const int kk0 = tid / 96,         dd0 = tid % 96;
    const int kk1 = (tid + 256) / 96, dd1 = (tid + 256) % 96;
    const int kk2 = (tid + 512) / 96, dd2 = (tid + 512) % 96;
    const int brow = tid >> 5;
    const int bc   = (tid & 31) * 4;
    float acc[6][8];
    #pragma unroll
    for (int i = 0; i < 6; i++)
        #pragma unroll
        for (int j = 0; j < 8; j++) acc[i][j] = 0.f;

    for (int n0 = 0; n0 < Ntok; n0 += 8) {
        float a0 = VC[(size_t)(n0 + kk0) * DP + dp0 + dd0];
        float a1 = VC[(size_t)(n0 + kk1) * DP + dp0 + dd1];
        float a2 = VC[(size_t)(n0 + kk2) * DP + dp0 + dd2];
        float4 pv = *(const float4*)&P[(size_t)(n0 + brow) * Ntok + m0 + bc];
        float ri = rinv[n0 + brow];
        pv.x = pv.x * pv.x * ri; pv.y = pv.y * pv.y * ri;
        pv.z = pv.z * pv.z * ri; pv.w = pv.w * pv.w * ri;
        __syncthreads();
        As[kk0][dd0] = a0; As[kk1][dd1] = a1; As[kk2][dd2] = a2;
        *(float4*)&Bs[brow][bc] = pv;
        __syncthreads();
        #pragma unroll
        for (int kk = 0; kk < 8; kk++) {
            float ar[6], br[8];
            #pragma unroll
            for (int i = 0; i < 6; i++) ar[i] = As[kk][ty * 6 + i];
            #pragma unroll
            for (int j = 0; j < 8; j++) br[j] = Bs[kk][tx * 8 + j];
            #pragma unroll
            for (int i = 0; i < 6; i++)
                #pragma unroll
                for (int j = 0; j < 8; j++) acc[i][j] += ar[i] * br[j];
        }
    }
    #pragma unroll
    for (int j = 0; j < 8; j++) {
        float ci = g_cinv[bh * Ntok + m0 + tx * 8 + j];
        #pragma unroll
        for (int i = 0; i < 6; i++)
            g_f1[((size_t)bh * DP + dp0 + ty * 6 + i) * Ntok + m0 + tx * 8 + j] = acc[i][j] * ci;
    }
}

// ---------------------------------------------------------------- fund[d1,e] = sum_m f1[d1,m] * VC[m,e]
// BM=96 (d1), BN=96 (e), BK=8 (m), TM=TN=6
__global__ __launch_bounds__(256) void k_fund() {
    __shared__ float As[8][96];
    __shared__ float Bs[8][96];
    const int tid = threadIdx.x;
    const int bh  = blockIdx.z;
    const int e0  = blockIdx.x * 96;
    const int d10 = blockIdx.y * 96;
    const float* F1 = g_f1 + (size_t)bh * DP * Ntok;
    const float* VC = g_VC + (size_t)bh * Ntok * DP;
    const int ty = tid >> 4, tx = tid & 15;
    const int akk  = tid & 7;
    const int add0 = tid >> 3;              // 0..31 ; +32, +64
    const int bkk0 = tid / 96,         bee0 = tid % 96;
    const int bkk1 = (tid + 256) / 96, bee1 = (tid + 256) % 96;
    const int bkk2 = (tid + 512) / 96, bee2 = (tid + 512) % 96;
    float acc[6][6];
    #pragma unroll
    for (int i = 0; i < 6; i++)
        #pragma unroll
        for (int j = 0; j < 6; j++) acc[i][j] = 0.f;

    for (int m0 = 0; m0 < Ntok; m0 += 8) {
        float a0 = F1[(size_t)(d10 + add0)      * Ntok + m0 + akk];
        float a1 = F1[(size_t)(d10 + add0 + 32) * Ntok + m0 + akk];
        float a2 = F1[(size_t)(d10 + add0 + 64) * Ntok + m0 + akk];
        float b0 = VC[(size_t)(m0 + bkk0) * DP + e0 + bee0];
        float b1 = VC[(size_t)(m0 + bkk1) * DP + e0 + bee1];
        float b2 = VC[(size_t)(m0 + bkk2) * DP + e0 + bee2];
        __syncthreads();
        As[akk][add0] = a0; As[akk][add0 + 32] = a1; As[akk][add0 + 64] = a2;
        Bs[bkk0][bee0] = b0; Bs[bkk1][bee1] = b1; Bs[bkk2][bee2] = b2;
        __syncthreads();
        #pragma unroll
        for (int kk = 0; kk < 8; kk++) {
            float ar[6], br[6];
            #pragma unroll
            for (int i = 0; i < 6; i++) ar[i] = As[kk][ty * 6 + i];
            #pragma unroll
            for (int j = 0; j < 6; j++) br[j] = Bs[kk][tx * 6 + j];
            #pragma unroll
            for (int i = 0; i < 6; i++)
                #pragma unroll
                for (int j = 0; j < 6; j++) acc[i][j] += ar[i] * br[j];
        }
    }
    #pragma unroll
    for (int i = 0; i < 6; i++)
        #pragma unroll
        for (int j = 0; j < 6; j++)
            g_fund[((size_t)bh * DP + d10 + ty * 6 + i) * DP + e0 + tx * 6 + j] = acc[i][j];
}

// ---------------------------------------------------------------- out[b,d2,c] = sum_{h,d1} fund[b,h,d1,d2] * Wpf[c, h*262+d1] + bpf[c]
__global__ __launch_bounds__(256) void k_out(const float* __restrict__ Wpf,
                                             const float* __restrict__ bpf,
                                             float* __restrict__ out) {
    __shared__ float As[8][128];
    __shared__ float Bs[8][128];
    const int tid = threadIdx.x;
    const int b   = blockIdx.z;
    const int c0  = blockIdx.x * 128;
    const int d20 = blockIdx.y * 128;
    const int ty = tid >> 4, tx = tid & 15;
    const int akk0 = tid >> 7;     // 0..1 ; +2*i
    const int add  = tid & 127;
    const int bkk  = tid & 7;
    const int bcc0 = tid >> 3;     // 0..31 ; +32*i
    float acc[8][8];
    #pragma unroll
    for (int i = 0; i < 8; i++)
        #pragma unroll
        for (int j = 0; j < 8; j++) acc[i][j] = 0.f;

    for (int k0 = 0; k0 < KPF; k0 += 8) {
        float av[4], bv[4];
        #pragma unroll
        for (int i = 0; i < 4; i++) {
            int k  = k0 + akk0 + 2 * i;
            int d2 = d20 + add;
            float v = 0.f;
            if (k < KPF && d2 < DP) {
                int h = k / Dv, d1 = k % Dv;
                v = g_fund[((size_t)(b * Hh + h) * DP + d1) * DP + d2];
            }
            av[i] = v;
        }
        #pragma unroll
        for (int i = 0; i < 4; i++) {
            int k = k0 + bkk;
            int cc = bcc0 + 32 * i;
            bv[i] = (k < KPF) ? Wpf[(size_t)(c0 + cc) * KPF + k] : 0.f;
        }
        __syncthreads();
        #pragma unroll
        for (int i = 0; i < 4; i++) {
            As[akk0 + 2 * i][add]  = av[i];
            Bs[bkk][bcc0 + 32 * i] = bv[i];
        }
        __syncthreads();
        #pragma unroll
        for (int kk = 0; kk < 8; kk++) {
            float ar[8], br[8];
            #pragma unroll
            for (int i = 0; i < 8; i++) ar[i] = As[kk][ty * 8 + i];
            #pragma unroll
            for (int j = 0; j < 8; j++) br[j] = Bs[kk][tx * 8 + j];
            #pragma unroll
            for (int i = 0; i < 8; i++)
                #pragma unroll
                for (int j = 0; j < 8; j++) acc[i][j] += ar[i] * br[j];
        }
    }
    #pragma unroll
    for (int j = 0; j < 8; j++) {
        int c = c0 + tx * 8 + j;
        float bias = bpf[c];
        #pragma unroll
        for (int i = 0; i < 8; i++) {
            int d2 = d20 + ty * 8 + i;
            if (d2 < Dv)
                out[((size_t)b * Dv + d2) * DIMC + c] = acc[i][j] + bias;
        }
    }
}

// ---------------------------------------------------------------- launch
extern "C" void kernel_launch(void* const* d_in, const int* in_sizes, int n_in,
                              void* d_out, int out_size) {
    const float* x    = (const float*)d_in[0];
    const float* Wqkv = (const float*)d_in[1];
    const float* Wpf  = (const float*)d_in[2];
    const float* bpf  = (const float*)d_in[3];
    float* out = (float*)d_out;

    k_zero <<<(BH * Ntok + 255) / 256, 256>>>();
    k_qkv  <<<dim3(18, 96), 256>>>(x, Wqkv);
    k_vcat <<<(BH * Ntok * DP + 255) / 256, 256>>>();
    k_scores<<<dim3(24, 24, BH), 256>>>();
    k_recip<<<(BH * Ntok + 255) / 256, 256>>>();
    k_f1   <<<dim3(24, 3, BH), 256>>>();
    k_fund <<<dim3(3, 3, BH), 256>>>();
    k_out  <<<dim3(6, 3, Bsz), 256>>>(Wpf, bpf, out);
}

// round 10
// speedup vs baseline: 1.4269x; 1.4269x over previous
#include <cuda_runtime.h>
#include <cuda_bf16.h>
#include <math.h>
#include <stdint.h>

#define Bsz  4
#define Ntok 3072
#define DIMC 768
#define Hh   3
#define HD   256
#define BH   (Bsz * Hh)          // 12
#define Dv   262                 // HD + 6
#define DP   288                 // padded per-head dim
#define NN   ((size_t)Ntok * Ntok)
#define KPF  786                 // DIM + 6*H
#define SROW 34                  // smem row stride in bf16 halves (17 words, odd -> conflict-free)

// -------- scratch (static device globals; no runtime allocation) --------
__device__ float g_QKV[3 * BH * Ntok * HD];
__device__ float g_VC [BH * Ntok * DP];
__device__ float g_P  [(size_t)BH * Ntok * Ntok];
__device__ float g_rsum[BH * Ntok];
__device__ float g_csum[BH * Ntok];
__device__ float g_rinv[BH * Ntok];
__device__ float g_cinv[BH * Ntok];
__device__ float g_f1 [BH * DP * Ntok];
__device__ float g_fund[BH * DP * DP];

// ---------------------------------------------------------------- helpers
__device__ __forceinline__ void mma_bf16(float* c, const uint32_t* a, const uint32_t* b) {
    asm volatile(
        "mma.sync.aligned.m16n8k16.row.col.f32.bf16.bf16.f32 "
        "{%0,%1,%2,%3}, {%4,%5,%6,%7}, {%8,%9}, {%0,%1,%2,%3};\n"
        : "+f"(c[0]), "+f"(c[1]), "+f"(c[2]), "+f"(c[3])
        : "r"(a[0]), "r"(a[1]), "r"(a[2]), "r"(a[3]), "r"(b[0]), "r"(b[1]));
}

// split float4 into bf16-hi pairs and bf16-lo (residual) pairs, packed 2 halves/word
__device__ __forceinline__ void split4(float4 v, uint32_t* oh, uint32_t* ol) {
    __nv_bfloat162 hA = __floats2bfloat162_rn(v.x, v.y);
    __nv_bfloat162 hB = __floats2bfloat162_rn(v.z, v.w);
    float rx = v.x - __bfloat162float(__low2bfloat16(hA));
    float ry = v.y - __bfloat162float(__high2bfloat16(hA));
    float rz = v.z - __bfloat162float(__low2bfloat16(hB));
    float rw = v.w - __bfloat162float(__high2bfloat16(hB));
    __nv_bfloat162 lA = __floats2bfloat162_rn(rx, ry);
    __nv_bfloat162 lB = __floats2bfloat162_rn(rz, rw);
    oh[0] = *(uint32_t*)&hA; oh[1] = *(uint32_t*)&hB;
    ol[0] = *(uint32_t*)&lA; ol[1] = *(uint32_t*)&lB;
}

__device__ __forceinline__ void split1(float v, __nv_bfloat16& h, __nv_bfloat16& l) {
    h = __float2bfloat16(v);
    l = __float2bfloat16(v - __bfloat162float(h));
}

// ---------------------------------------------------------------- zero sums
__global__ void k_zero() {
    int i = blockIdx.x * 256 + threadIdx.x;
    if (i < BH * Ntok) { g_rsum[i] = 0.f; g_csum[i] = 0.f; }
}

// ---------------------------------------------------------------- QKV GEMM (bf16x3 tensor)
// C[12288, 2304] = x @ Wqkv^T, BM=BN=128, BK=32
__global__ __launch_bounds__(256) void k_qkv(const float* __restrict__ x,
                                             const float* __restrict__ Wqkv) {
    __shared__ __nv_bfloat16 Ah[128*SROW], Al[128*SROW], Bh[128*SROW], Bl[128*SROW];
    const int tid  = threadIdx.x;
    const int m0   = blockIdx.y * 128;
    const int n0   = blockIdx.x * 128;
    const int lrow = tid >> 1;
    const int lseg = (tid & 1) * 16;
    const int warp = tid >> 5, lane = tid & 31;
    const int g = lane >> 2, tg = lane & 3;
    const int wm = warp >> 1, wn = warp & 1;
    float c[2][8][4];
    #pragma unroll
    for (int i = 0; i < 2; i++)
        #pragma unroll
        for (int j = 0; j < 8; j++)
            #pragma unroll
            for (int r = 0; r < 4; r++) c[i][j][r] = 0.f;

    for (int k0 = 0; k0 < 768; k0 += 32) {
        float4 av[4], bv[4];
        #pragma unroll
        for (int i = 0; i < 4; i++) {
            av[i] = *(const float4*)&x   [(size_t)(m0 + lrow) * 768 + k0 + lseg + 4*i];
            bv[i] = *(const float4*)&Wqkv[(size_t)(n0 + lrow) * 768 + k0 + lseg + 4*i];
        }
        __syncthreads();
        #pragma unroll
        for (int i = 0; i < 4; i++) {
            uint32_t h[2], l[2];
            split4(av[i], h, l);
            *(uint32_t*)&Ah[lrow*SROW + lseg + 4*i]     = h[0];
            *(uint32_t*)&Ah[lrow*SROW + lseg + 4*i + 2] = h[1];
            *(uint32_t*)&Al[lrow*SROW + lseg + 4*i]     = l[0];
            *(uint32_t*)&Al[lrow*SROW + lseg + 4*i + 2] = l[1];
            split4(bv[i], h, l);
            *(uint32_t*)&Bh[lrow*SROW + lseg + 4*i]     = h[0];
            *(uint32_t*)&Bh[lrow*SROW + lseg + 4*i + 2] = h[1];
            *(uint32_t*)&Bl[lrow*SROW + lseg + 4*i]     = l[0];
            *(uint32_t*)&Bl[lrow*SROW + lseg + 4*i + 2] = l[1];
        }
        __syncthreads();
        #pragma unroll
        for (int kk = 0; kk < 32; kk += 16) {
            uint32_t ah[2][4], al[2][4];
            #pragma unroll
            for (int mt = 0; mt < 2; mt++) {
                int base = (wm*32 + mt*16 + g)*SROW + kk + tg*2;
                ah[mt][0] = *(uint32_t*)&Ah[base];
                ah[mt][1] = *(uint32_t*)&Ah[base + 8*SROW];
                ah[mt][2] = *(uint32_t*)&Ah[base + 8];
                ah[mt][3] = *(uint32_t*)&Ah[base + 8*SROW + 8];
                al[mt][0] = *(uint32_t*)&Al[base];
                al[mt][1] = *(uint32_t*)&Al[base + 8*SROW];
                al[mt][2] = *(uint32_t*)&Al[base + 8];
                al[mt][3] = *(uint32_t*)&Al[base + 8*SROW + 8];
            }
            uint32_t bhf[8][2], blf[8][2];
            #pragma unroll
            for (int nt = 0; nt < 8; nt++) {
                int base = (wn*64 + nt*8 + g)*SROW + kk + tg*2;
                bhf[nt][0] = *(uint32_t*)&Bh[base];
                bhf[nt][1] = *(uint32_t*)&Bh[base + 8];
                blf[nt][0] = *(uint32_t*)&Bl[base];
                blf[nt][1] = *(uint32_t*)&Bl[base + 8];
            }
            #pragma unroll
            for (int mt = 0; mt < 2; mt++)
                #pragma unroll
                for (int nt = 0; nt < 8; nt++) {
                    mma_bf16(c[mt][nt], ah[mt], bhf[nt]);
                    mma_bf16(c[mt][nt], ah[mt], blf[nt]);
                    mma_bf16(c[mt][nt], al[mt], bhf[nt]);
                }
        }
    }
    #pragma unroll
    for (int mt = 0; mt < 2; mt++)
        #pragma unroll
        for (int nt = 0; nt < 8; nt++)
            #pragma unroll
            for (int r = 0; r < 4; r++) {
                int m  = m0 + wm*32 + mt*16 + g + (r >> 1) * 8;
                int cc = n0 + wn*64 + nt*8 + tg*2 + (r & 1);
                int bq = m / Ntok, n = m % Ntok;
                int t = cc / 768, rr = cc % 768;
                int h = rr >> 8, d = rr & 255;
                g_QKV[(((size_t)(t * Bsz + bq) * Hh + h) * Ntok + n) * HD + d] = c[mt][nt][r];
            }
}

// ---------------------------------------------------------------- v_cat build
__global__ void k_vcat() {
    int i = blockIdx.x * 256 + threadIdx.x;
    const int total = BH * Ntok * DP;
    if (i >= total) return;
    int j    = i % DP;
    int rest = i / DP;
    int n    = rest % Ntok;
    int bh   = rest / Ntok;
    float val;
    if (j < 256) {
        val = g_QKV[((size_t)(2 * BH + bh) * Ntok + n) * HD + j];
    } else if (j < 262) {
        float p3 = -1.f + 2.f * (float)(n % 48) / 47.f;
        float p4 = -1.f + 2.f * (float)(n / 48) / 63.f;
        int c = j - 256;
        val = (c == 0) ? p3 * p3 :
              (c == 1) ? p4 * p4 :
              (c == 2) ? p3 * p4 :
              (c == 3) ? p3 :
              (c == 4) ? p4 : 1.f;
    } else {
        val = 0.f;
    }
    g_VC[i] = val;
}

// ---------------------------------------------------------------- scores (bf16x3 tensor): P = exp(Q K^T / 16)
__global__ __launch_bounds__(256) void k_scores() {
    __shared__ __nv_bfloat16 Ah[128*SROW], Al[128*SROW], Bh[128*SROW], Bl[128*SROW];
    __shared__ float rAcc[128], cAcc[128];
    const int tid = threadIdx.x;
    const int bh  = blockIdx.z;
    const int m0  = blockIdx.y * 128;   // query rows
    const int c0  = blockIdx.x * 128;   // key cols
    const float* Q  = g_QKV + (size_t)bh * Ntok * HD;
    const float* Km = g_QKV + (size_t)(BH + bh) * Ntok * HD;
    if (tid < 128) { rAcc[tid] = 0.f; cAcc[tid] = 0.f; }
    const int lrow = tid >> 1;
    const int lseg = (tid & 1) * 16;
    const int warp = tid >> 5, lane = tid & 31;
    const int g = lane >> 2, tg = lane & 3;
    const int wm = warp >> 1, wn = warp & 1;
    float c[2][8][4];
    #pragma unroll
    for (int i = 0; i < 2; i++)
        #pragma unroll
        for (int j = 0; j < 8; j++)
            #pragma unroll
            for (int r = 0; r < 4; r++) c[i][j][r] = 0.f;

    for (int k0 = 0; k0 < HD; k0 += 32) {
        float4 av[4], bv[4];
        #pragma unroll
        for (int i = 0; i < 4; i++) {
            av[i] = *(const float4*)&Q [(size_t)(m0 + lrow) * HD + k0 + lseg + 4*i];
            bv[i] = *(const float4*)&Km[(size_t)(c0 + lrow) * HD + k0 + lseg + 4*i];
        }
        __syncthreads();
        #pragma unroll
        for (int i = 0; i < 4; i++) {
            uint32_t h[2], l[2];
            split4(av[i], h, l);
            *(uint32_t*)&Ah[lrow*SROW + lseg + 4*i]     = h[0];
            *(uint32_t*)&Ah[lrow*SROW + lseg + 4*i + 2] = h[1];
            *(uint32_t*)&Al[lrow*SROW + lseg + 4*i]     = l[0];
            *(uint32_t*)&Al[lrow*SROW + lseg + 4*i + 2] = l[1];
            split4(bv[i], h, l);
            *(uint32_t*)&Bh[lrow*SROW + lseg + 4*i]     = h[0];
            *(uint32_t*)&Bh[lrow*SROW + lseg + 4*i + 2] = h[1];
            *(uint32_t*)&Bl[lrow*SROW + lseg + 4*i]     = l[0];
            *(uint32_t*)&Bl[lrow*SROW + lseg + 4*i + 2] = l[1];
        }
        __syncthreads();
        #pragma unroll
        for (int kk = 0; kk < 32; kk += 16) {
            uint32_t ah[2][4], al[2][4];
            #pragma unroll
            for (int mt = 0; mt < 2; mt++) {
                int base = (wm*32 + mt*16 + g)*SROW + kk + tg*2;
                ah[mt][0] = *(uint32_t*)&Ah[base];
                ah[mt][1] = *(uint32_t*)&Ah[base + 8*SROW];
                ah[mt][2] = *(uint32_t*)&Ah[base + 8];
                ah[mt][3] = *(uint32_t*)&Ah[base + 8*SROW + 8];
                al[mt][0] = *(uint32_t*)&Al[base];
                al[mt][1] = *(uint32_t*)&Al[base + 8*SROW];
                al[mt][2] = *(uint32_t*)&Al[base + 8];
                al[mt][3] = *(uint32_t*)&Al[base + 8*SROW + 8];
            }
            uint32_t bhf[8][2], blf[8][2];
            #pragma unroll
            for (int nt = 0; nt < 8; nt++) {
                int base = (wn*64 + nt*8 + g)*SROW + kk + tg*2;
                bhf[nt][0] = *(uint32_t*)&Bh[base];
                bhf[nt][1] = *(uint32_t*)&Bh[base + 8];
                blf[nt][0] = *(uint32_t*)&Bl[base];
                blf[nt][1] = *(uint32_t*)&Bl[base + 8];
            }
            #pragma unroll
            for (int mt = 0; mt < 2; mt++)
                #pragma unroll
                for (int nt = 0; nt < 8; nt++) {
                    mma_bf16(c[mt][nt], ah[mt], bhf[nt]);
                    mma_bf16(c[mt][nt], ah[mt], blf[nt]);
                    mma_bf16(c[mt][nt], al[mt], bhf[nt]);
                }
        }
    }
    // exp + sums + store
    float rp[2][2] = {{0.f,0.f},{0.f,0.f}};
    float cp[8][2];
    #pragma unroll
    for (int nt = 0; nt < 8; nt++) { cp[nt][0] = 0.f; cp[nt][1] = 0.f; }
    #pragma unroll
    for (int mt = 0; mt < 2; mt++)
        #pragma unroll
        for (int nt = 0; nt < 8; nt++)
            #pragma unroll
            for (int r = 0; r < 4; r++) {
                float e = __expf(c[mt][nt][r] * 0.0625f);
                c[mt][nt][r] = e;
                rp[mt][r >> 1] += e;
                cp[nt][r & 1]  += e;
            }
    #pragma unroll
    for (int mt = 0; mt < 2; mt++)
        #pragma unroll
        for (int nt = 0; nt < 8; nt++)
            #pragma unroll
            for (int rh = 0; rh < 2; rh++) {
                int row = m0 + wm*32 + mt*16 + g + rh*8;
                int col = c0 + wn*64 + nt*8 + tg*2;
                *(float2*)&g_P[(size_t)bh * NN + (size_t)row * Ntok + col] =
                    make_float2(c[mt][nt][rh*2], c[mt][nt][rh*2 + 1]);
            }
    #pragma unroll
    for (int mt = 0; mt < 2; mt++)
        #pragma unroll
        for (int rh = 0; rh < 2; rh++)
            atomicAdd(&rAcc[wm*32 + mt*16 + g + rh*8], rp[mt][rh]);
    #pragma unroll
    for (int nt = 0; nt < 8; nt++)
        #pragma unroll
        for (int cb = 0; cb < 2; cb++)
            atomicAdd(&cAcc[wn*64 + nt*8 + tg*2 + cb], cp[nt][cb]);
    __syncthreads();
    if (tid < 128) {
        atomicAdd(&g_rsum[bh * Ntok + m0 + tid], rAcc[tid]);
        atomicAdd(&g_csum[bh * Ntok + c0 + tid], cAcc[tid]);
    }
}

// ---------------------------------------------------------------- reciprocals
__global__ void k_recip() {
    int i = blockIdx.x * 256 + threadIdx.x;
    if (i < BH * Ntok) {
        g_rinv[i] = 1.f / g_rsum[i];
        g_cinv[i] = 1.f / g_csum[i];
    }
}

// ---------------------------------------------------------------- f1 (bf16x3 tensor)
// f1[dp,m] = cinv[m] * sum_n VC[n,dp] * (P[n,m]^2 * rinv[n]),  BM=64(dp), BN=128(m), BK=32(n)
__global__ __launch_bounds__(256) void k_f1() {
    __shared__ __nv_bfloat16 Ah[64*SROW], Al[64*SROW], Bh[128*SROW], Bl[128*SROW];
    const int tid = threadIdx.x;
    const int bh  = blockIdx.z;
    const int m0  = blockIdx.x * 128;
    const int dp0 = blockIdx.y * 64;
    const float* VC   = g_VC + (size_t)bh * Ntok * DP;
    const float* P    = g_P  + (size_t)bh * NN;
    const float* rinv = g_rinv + bh * Ntok;
    const int warp = tid >> 5, lane = tid & 31;
    const int g = lane >> 2, tg = lane & 3;
    const int wm = warp >> 2, wn = warp & 3;   // 2 x 4 warp grid
    const int ln = tid >> 3;                   // n within tile (0..31)
    const int lc = tid & 7;                    // 8 column segments
    float c[2][4][4];
    #pragma unroll
    for (int i = 0; i < 2; i++)
        #pragma unroll
        for (int j = 0; j < 4; j++)
            #pragma unroll
            for (int r = 0; r < 4; r++) c[i][j][r] = 0.f;

    for (int n0 = 0; n0 < Ntok; n0 += 32) {
        float4 av[2], bv[4];
        #pragma unroll
        for (int i = 0; i < 2; i++) {
            int col = dp0 + lc*8 + 4*i;
            av[i] = (col < DP) ? *(const float4*)&VC[(size_t)(n0 + ln) * DP + col]
                               : make_float4(0.f, 0.f, 0.f, 0.f);
        }
        float ri = rinv[n0 + ln];
        #pragma unroll
        for (int i = 0; i < 4; i++) {
            float4 p = *(const float4*)&P[(size_t)(n0 + ln) * Ntok + m0 + lc*16 + 4*i];
            p.x = p.x * p.x * ri; p.y = p.y * p.y * ri;
            p.z = p.z * p.z * ri; p.w = p.w * p.w * ri;
            bv[i] = p;
        }
        __syncthreads();
        // transposed stores: As[dp_local][n], Bs[m_local][n]
        #pragma unroll
        for (int i = 0; i < 2; i++) {
            float vals[4] = {av[i].x, av[i].y, av[i].z, av[i].w};
            #pragma unroll
            for (int j = 0; j < 4; j++) {
                __nv_bfloat16 h, l;
                split1(vals[j], h, l);
                int cc = lc*8 + 4*i + j;
                Ah[cc*SROW + ln] = h;
                Al[cc*SROW + ln] = l;
            }
        }
        #pragma unroll
        for (int i = 0; i < 4; i++) {
            float vals[4] = {bv[i].x, bv[i].y, bv[i].z, bv[i].w};
            #pragma unroll
            for (int j = 0; j < 4; j++) {
                __nv_bfloat16 h, l;
                split1(vals[j], h, l);
                int mm = lc*16 + 4*i + j;
                Bh[mm*SROW + ln] = h;
                Bl[mm*SROW + ln] = l;
            }
        }
        __syncthreads();
        #pragma unroll
        for (int kk = 0; kk < 32; kk += 16) {
            uint32_t ah[2][4], al[2][4];
            #pragma unroll
            for (int mt = 0; mt < 2; mt++) {
                int base = (wm*32 + mt*16 + g)*SROW + kk + tg*2;
                ah[mt][0] = *(uint32_t*)&Ah[base];
                ah[mt][1] = *(uint32_t*)&Ah[base + 8*SROW];
                ah[mt][2] = *(uint32_t*)&Ah[base + 8];
                ah[mt][3] = *(uint32_t*)&Ah[base + 8*SROW + 8];
                al[mt][0] = *(uint32_t*)&Al[base];
                al[mt][1] = *(uint32_t*)&Al[base + 8*SROW];
                al[mt][2] = *(uint32_t*)&Al[base + 8];
                al[mt][3] = *(uint32_t*)&Al[base + 8*SROW + 8];
            }
            uint32_t bhf[4][2], blf[4][2];
            #pragma unroll
            for (int nt = 0; nt < 4; nt++) {
                int base = (wn*32 + nt*8 + g)*SROW + kk + tg*2;
                bhf[nt][0] = *(uint32_t*)&Bh[base];
                bhf[nt][1] = *(uint32_t*)&Bh[base + 8];
                blf[nt][0] = *(uint32_t*)&Bl[base];
                blf[nt][1] = *(uint32_t*)&Bl[base + 8];
            }
            #pragma unroll
            for (int mt = 0; mt < 2; mt++)
                #pragma unroll
                for (int nt = 0; nt < 4; nt++) {
                    mma_bf16(c[mt][nt], ah[mt], bhf[nt]);
                    mma_bf16(c[mt][nt], ah[mt], blf[nt]);
                    mma_bf16(c[mt][nt], al[mt], bhf[nt]);
                }
        }
    }
    #pragma unroll
    for (int mt = 0; mt < 2; mt++)
        #pragma unroll
        for (int nt = 0; nt < 4; nt++)
            #pragma unroll
            for (int rh = 0; rh < 2; rh++) {
                int dpg = dp0 + wm*32 + mt*16 + g + rh*8;
                if (dpg < DP) {
                    int col = m0 + wn*32 + nt*8 + tg*2;
                    float ci0 = g_cinv[bh * Ntok + col];
                    float ci1 = g_cinv[bh * Ntok + col + 1];
                    *(float2*)&g_f1[((size_t)bh * DP + dpg) * Ntok + col] =
                        make_float2(c[mt][nt][rh*2] * ci0, c[mt][nt][rh*2 + 1] * ci1);
                }
            }
}

// ---------------------------------------------------------------- fund[d1,e] = sum_m f1[d1,m] * VC[m,e]  (SIMT fp32)
__global__ __launch_bounds__(256) void k_fund() {
    __shared__ float As[8][96];
    __shared__ float Bs[8][96];
    const int tid = threadIdx.x;
    const int bh  = blockIdx.z;
    const int e0  = blockIdx.x * 96;
    const int d10 = blockIdx.y * 96;
    const float* F1 = g_f1 + (size_t)bh * DP * Ntok;
    const float* VC = g_VC + (size_t)bh * Ntok * DP;
    const int ty = tid >> 4, tx = tid & 15;
    const int akk  = tid & 7;
    const int add0 = tid >> 3;
    const int bkk0 = tid / 96,         bee0 = tid % 96;
    const int bkk1 = (tid + 256) / 96, bee1 = (tid + 256) % 96;
    const int bkk2 = (tid + 512) / 96, bee2 = (tid + 512) % 96;
    float acc[6][6];
    #pragma unroll
    for (int i = 0; i < 6; i++)
        #pragma unroll
        for (int j = 0; j < 6; j++) acc[i][j] = 0.f;

    for (int m0 = 0; m0 < Ntok; m0 += 8) {
        float a0 = F1[(size_t)(d10 + add0)      * Ntok + m0 + akk];
        float a1 = F1[(size_t)(d10 + add0 + 32) * Ntok + m0 + akk];
        float a2 = F1[(size_t)(d10 + add0 + 64) * Ntok + m0 + akk];
        float b0 = VC[(size_t)(m0 + bkk0) * DP + e0 + bee0];
        float b1 = VC[(size_t)(m0 + bkk1) * DP + e0 + bee1];
        float b2 = VC[(size_t)(m0 + bkk2) * DP + e0 + bee2];
        __syncthreads();
        As[akk][add0] = a0; As[akk][add0 + 32] = a1; As[akk][add0 + 64] = a2;
        Bs[bkk0][bee0] = b0; Bs[bkk1][bee1] = b1; Bs[bkk2][bee2] = b2;
        __syncthreads();
        #pragma unroll
        for (int kk = 0; kk < 8; kk++) {
            float ar[6], br[6];
            #pragma unroll
            for (int i = 0; i < 6; i++) ar[i] = As[kk][ty * 6 + i];
            #pragma unroll
            for (int j = 0; j < 6; j++) br[j] = Bs[kk][tx * 6 + j];
            #pragma unroll
            for (int i = 0; i < 6; i++)
                #pragma unroll
                for (int j = 0; j < 6; j++) acc[i][j] += ar[i] * br[j];
        }
    }
    #pragma unroll
    for (int i = 0; i < 6; i++)
        #pragma unroll
        for (int j = 0; j < 6; j++)
            g_fund[((size_t)bh * DP + d10 + ty * 6 + i) * DP + e0 + tx * 6 + j] = acc[i][j];
}

// ---------------------------------------------------------------- out GEMM (SIMT fp32)
__global__ __launch_bounds__(256) void k_out(const float* __restrict__ Wpf,
                                             const float* __restrict__ bpf,
                                             float* __restrict__ out) {
    __shared__ float As[8][128];
    __shared__ float Bs[8][128];
    const int tid = threadIdx.x;
    const int b   = blockIdx.z;
    const int c0  = blockIdx.x * 128;
    const int d20 = blockIdx.y * 128;
    const int ty = tid >> 4, tx = tid & 15;
    const int akk0 = tid >> 7;
    const int add  = tid & 127;
    const int bkk  = tid & 7;
    const int bcc0 = tid >> 3;
    float acc[8][8];
    #pragma unroll
    for (int i = 0; i < 8; i++)
        #pragma unroll
        for (int j = 0; j < 8; j++) acc[i][j] = 0.f;

    for (int k0 = 0; k0 < KPF; k0 += 8) {
        float av[4], bv[4];
        #pragma unroll
        for (int i = 0; i < 4; i++) {
            int k  = k0 + akk0 + 2 * i;
            int d2 = d20 + add;
            float v = 0.f;
            if (k < KPF && d2 < DP) {
                int h = k / Dv, d1 = k % Dv;
                v = g_fund[((size_t)(b * Hh + h) * DP + d1) * DP + d2];
            }
            av[i] = v;
        }
        #pragma unroll
        for (int i = 0; i < 4; i++) {
            int k = k0 + bkk;
            int cc = bcc0 + 32 * i;
            bv[i] = (k < KPF) ? Wpf[(size_t)(c0 + cc) * KPF + k] : 0.f;
        }
        __syncthreads();
        #pragma unroll
        for (int i = 0; i < 4; i++) {
            As[akk0 + 2 * i][add]  = av[i];
            Bs[bkk][bcc0 + 32 * i] = bv[i];
        }
        __syncthreads();
        #pragma unroll
        for (int kk = 0; kk < 8; kk++) {
            float ar[8], br[8];
            #pragma unroll
            for (int i = 0; i < 8; i++) ar[i] = As[kk][ty * 8 + i];
            #pragma unroll
            for (int j = 0; j < 8; j++) br[j] = Bs[kk][tx * 8 + j];
            #pragma unroll
            for (int i = 0; i < 8; i++)
                #pragma unroll
                for (int j = 0; j < 8; j++) acc[i][j] += ar[i] * br[j];
        }
    }
    #pragma unroll
    for (int j = 0; j < 8; j++) {
        int c = c0 + tx * 8 + j;
        float bias = bpf[c];
        #pragma unroll
        for (int i = 0; i < 8; i++) {
            int d2 = d20 + ty * 8 + i;
            if (d2 < Dv)
                out[((size_t)b * Dv + d2) * DIMC + c] = acc[i][j] + bias;
        }
    }
}

// ---------------------------------------------------------------- launch
extern "C" void kernel_launch(void* const* d_in, const int* in_sizes, int n_in,
                              void* d_out, int out_size) {
    const float* x    = (const float*)d_in[0];
    const float* Wqkv = (const float*)d_in[1];
    const float* Wpf  = (const float*)d_in[2];
    const float* bpf  = (const float*)d_in[3];
    float* out = (float*)d_out;

    k_zero <<<(BH * Ntok + 255) / 256, 256>>>();
    k_qkv  <<<dim3(18, 96), 256>>>(x, Wqkv);
    k_vcat <<<(BH * Ntok * DP + 255) / 256, 256>>>();
    k_scores<<<dim3(24, 24, BH), 256>>>();
    k_recip<<<(BH * Ntok + 255) / 256, 256>>>();
    k_f1   <<<dim3(24, 5, BH), 256>>>();
    k_fund <<<dim3(3, 3, BH), 256>>>();
    k_out  <<<dim3(6, 3, Bsz), 256>>>(Wpf, bpf, out);
}